// round 7
// baseline (speedup 1.0000x reference)
#include <cuda_runtime.h>
#include <cstdint>

// out[b, n, :] = (cnn[b] @ Wkv[:, 768:1536]) @ Wp + bp   (independent of n)
// image_patches and Wq are dead: softmax over kv_len=1 -> attn == 1.
//
// 2 launches:
//   chain_kernel (384 CTAs, persistent, 3 grid barriers):
//     gemm1 partials -> reduce1 -> gemm2 partials -> reduce2(+bias) -> g_y
//   bcast_kernel (1152 CTAs): broadcast g_y over N=576 via TMA bulk stores.

#define B_SZ   64
#define N_SEQ  576
#define C_DIM  768
#define K1     2048
#define LDKV   1536

#define NBLK   384             // all resident at occ 3 (148*3 = 444 >= 384)
#define NT1    12              // gemm1: 12 n-tiles of 64
#define KS1    32              // gemm1: 32 k-splits of 64 -> 384 units
#define KC1    64
#define NT2    12              // gemm2: 12 n-tiles of 64
#define KS2    16              // gemm2: 16 k-splits of 48 -> 192 units
#define KC2    48
#define BC_CH  18              // bcast: 18 chunks of 32 rows -> 1152 blocks

__device__ float g_p1[KS1 * B_SZ * C_DIM];   // gemm1 partials (6.3 MB, L2-resident)
__device__ float g_v [B_SZ * C_DIM];
__device__ float g_p2[KS2 * B_SZ * C_DIM];   // gemm2 partials (3 MB)
__device__ float g_y [B_SZ * C_DIM];
__device__ unsigned g_barcnt = 0;
__device__ unsigned g_bargen = 0;            // monotonic across graph replays

// ---- packed f32x2 (FFMA2) ----
__device__ __forceinline__ unsigned long long pack2(float x) {
    unsigned long long r; unsigned xi = __float_as_uint(x);
    asm("mov.b64 %0, {%1, %1};" : "=l"(r) : "r"(xi));
    return r;
}
__device__ __forceinline__ void fma2(unsigned long long& d,
                                     unsigned long long a, unsigned long long b) {
    asm("fma.rn.f32x2 %0, %1, %2, %0;" : "+l"(d) : "l"(a), "l"(b));
}
__device__ __forceinline__ float2 u2f(unsigned long long u) {
    float2 f; asm("mov.b64 {%0, %1}, %2;" : "=f"(f.x), "=f"(f.y) : "l"(u));
    return f;
}
__device__ __forceinline__ uint32_t smem_u32(const void* p) {
    uint32_t a;
    asm("{ .reg .u64 t; cvta.to.shared.u64 t, %1; cvt.u32.u64 %0, t; }" : "=r"(a) : "l"(p));
    return a;
}

// Sense-reversing grid barrier; all NBLK CTAs resident -> no deadlock.
__device__ __forceinline__ void grid_barrier() {
    __syncthreads();
    if (threadIdx.x == 0) {
        unsigned gen = *(volatile unsigned*)&g_bargen;    // read BEFORE arriving
        __threadfence();
        unsigned old = atomicAdd(&g_barcnt, 1);
        if (old == NBLK - 1) {
            g_barcnt = 0;
            __threadfence();
            atomicAdd(&g_bargen, 1);                      // release
        } else {
            while (*(volatile unsigned*)&g_bargen == gen) { }
        }
        __threadfence();
    }
    __syncthreads();
}

// 64-wide tile GEMM body: acc += A[64 x KCHUNK] * B[KCHUNK x 64]
template<int KCHUNK>
__device__ __forceinline__ void gemm_body(
    const float* __restrict__ A, int lda,
    const float* __restrict__ Bm, int ldb,
    float (*As)[68], float (*Bs)[64],
    unsigned long long acc[4][2])
{
    const int tid = threadIdx.x;
    const int tx = tid & 15, ty = tid >> 4;

    for (int kt = 0; kt < KCHUNK; kt += 16) {
        {
            int m = tid >> 2, kq = (tid & 3) * 4;
            float4 a = *(const float4*)&A[m * lda + kt + kq];
            As[kq+0][m] = a.x; As[kq+1][m] = a.y;
            As[kq+2][m] = a.z; As[kq+3][m] = a.w;
        }
        {
            int k = tid >> 4, n4 = (tid & 15) * 4;
            *(float4*)&Bs[k][n4] = *(const float4*)&Bm[(kt + k) * ldb + n4];
        }
        __syncthreads();
        #pragma unroll
        for (int k = 0; k < 16; ++k) {
            float4 a = *(const float4*)&As[k][ty * 4];
            ulonglong2 b = *(const ulonglong2*)&Bs[k][tx * 4];
            unsigned long long a0 = pack2(a.x), a1 = pack2(a.y);
            unsigned long long a2 = pack2(a.z), a3 = pack2(a.w);
            fma2(acc[0][0],a0,b.x); fma2(acc[0][1],a0,b.y);
            fma2(acc[1][0],a1,b.x); fma2(acc[1][1],a1,b.y);
            fma2(acc[2][0],a2,b.x); fma2(acc[2][1],a2,b.y);
            fma2(acc[3][0],a3,b.x); fma2(acc[3][1],a3,b.y);
        }
        __syncthreads();
    }
}

__global__ void __launch_bounds__(256, 3)
chain_kernel(const float* __restrict__ cnn, const float* __restrict__ Wkv,
             const float* __restrict__ Wp,  const float* __restrict__ bp)
{
    __shared__ float As[16][68];
    __shared__ float Bs[16][64];

    const int tid = threadIdx.x;
    const int cta = blockIdx.x;
    const int tx = tid & 15, ty = tid >> 4;

    // ---------- Phase 1: gemm1 partials (384 units) ----------
    {
        int ntile = cta % NT1;
        int split = cta / NT1;
        int n0 = ntile * 64;

        unsigned long long acc[4][2];
        #pragma unroll
        for (int i = 0; i < 4; ++i) { acc[i][0] = 0ull; acc[i][1] = 0ull; }

        gemm_body<KC1>(cnn + split * KC1, K1,
                       Wkv + (size_t)(split * KC1) * LDKV + C_DIM + n0, LDKV,
                       As, Bs, acc);

        float* Pout = g_p1 + split * (B_SZ * C_DIM) + n0;
        #pragma unroll
        for (int i = 0; i < 4; ++i) {
            float2 f0 = u2f(acc[i][0]), f1 = u2f(acc[i][1]);
            *(float4*)&Pout[(ty * 4 + i) * C_DIM + tx * 4] =
                make_float4(f0.x, f0.y, f1.x, f1.y);
        }
    }
    grid_barrier();

    // ---------- Phase 2: reduce1 -> g_v (384 CTAs x 32 float4) ----------
    if (tid < 32) {
        int idx = cta * 32 + tid;                        // 0..12287 float4
        const float4* p = (const float4*)g_p1;
        float4 s = make_float4(0.f, 0.f, 0.f, 0.f);
        #pragma unroll
        for (int sp = 0; sp < KS1; ++sp) {
            float4 t = p[sp * (B_SZ * C_DIM / 4) + idx];
            s.x += t.x; s.y += t.y; s.z += t.z; s.w += t.w;
        }
        ((float4*)g_v)[idx] = s;
    }
    grid_barrier();

    // ---------- Phase 3: gemm2 partials (192 units; CTAs >= 192 idle) ----------
    if (cta < NT2 * KS2) {
        int ntile = cta % NT2;
        int split = cta / NT2;
        int n0 = ntile * 64;

        unsigned long long acc[4][2];
        #pragma unroll
        for (int i = 0; i < 4; ++i) { acc[i][0] = 0ull; acc[i][1] = 0ull; }

        gemm_body<KC2>(g_v + split * KC2, C_DIM,
                       Wp + (size_t)(split * KC2) * C_DIM + n0, C_DIM,
                       As, Bs, acc);

        float* Pout = g_p2 + split * (B_SZ * C_DIM) + n0;
        #pragma unroll
        for (int i = 0; i < 4; ++i) {
            float2 f0 = u2f(acc[i][0]), f1 = u2f(acc[i][1]);
            *(float4*)&Pout[(ty * 4 + i) * C_DIM + tx * 4] =
                make_float4(f0.x, f0.y, f1.x, f1.y);
        }
    }
    grid_barrier();

    // ---------- Phase 4: reduce2 + bias -> g_y ----------
    if (tid < 32) {
        int idx = cta * 32 + tid;                        // 0..12287 float4
        const float4* p = (const float4*)g_p2;
        float4 s = ((const float4*)bp)[idx % (C_DIM / 4)];
        #pragma unroll
        for (int sp = 0; sp < KS2; ++sp) {
            float4 t = p[sp * (B_SZ * C_DIM / 4) + idx];
            s.x += t.x; s.y += t.y; s.z += t.z; s.w += t.w;
        }
        ((float4*)g_y)[idx] = s;
    }
}

// Broadcast g_y over N=576 via TMA bulk stores. 1152 blocks (proven 19.3us).
__global__ void __launch_bounds__(256)
bcast_kernel(float* __restrict__ out)
{
    __shared__ __align__(16) float ys[8 * C_DIM];   // 24 KB

    int b     = blockIdx.x / BC_CH;
    int chunk = blockIdx.x % BC_CH;
    const int tid = threadIdx.x;

    const float4* ysrc = (const float4*)(g_y + b * C_DIM);
    #pragma unroll
    for (int i = tid; i < 8 * (C_DIM / 4); i += 256)
        ((float4*)ys)[i] = ysrc[i % (C_DIM / 4)];
    __syncthreads();
    asm volatile("fence.proxy.async.shared::cta;" ::: "memory");

    if (tid < 4) {
        uint32_t s = smem_u32(ys);
        float* g = out + ((size_t)b * N_SEQ + chunk * 32 + tid * 8) * C_DIM;
        asm volatile("cp.async.bulk.global.shared::cta.bulk_group [%0], [%1], %2;"
                     :: "l"(g), "r"(s), "n"(8 * C_DIM * 4) : "memory");
        asm volatile("cp.async.bulk.commit_group;" ::: "memory");
        asm volatile("cp.async.bulk.wait_group 0;" ::: "memory");
    }
}

extern "C" void kernel_launch(void* const* d_in, const int* in_sizes, int n_in,
                              void* d_out, int out_size)
{
    (void)in_sizes; (void)n_in; (void)out_size;
    // Inputs: image_patches, cnn_feature_vector, Wq, Wkv, Wp, bp
    const float* cnn = (const float*)d_in[1];
    const float* Wkv = (const float*)d_in[3];
    const float* Wp  = (const float*)d_in[4];
    const float* bp  = (const float*)d_in[5];
    float* out = (float*)d_out;

    chain_kernel<<<NBLK, 256>>>(cnn, Wkv, Wp, bp);   // 384 blocks, persistent
    bcast_kernel<<<B_SZ * BC_CH, 256>>>(out);        // 1152 blocks
}

// round 8
// speedup vs baseline: 1.0639x; 1.0639x over previous
#include <cuda_runtime.h>
#include <cstdint>

// out[b, n, :] = (cnn[b] @ Wkv[:, 768:1536]) @ Wp + bp   (independent of n)
// image_patches and Wq are dead: softmax over kv_len=1 -> attn == 1.
//
// 3 launches, NO split-K scratch arrays (keeps working set < L2 so replay
// output stores stay L2-resident):
//   gemm1: 384 CTAs, REDG-accumulate v into g_v (g_v == 0 on entry: static
//          init on call 1, re-zeroed by bcast each call). Prologue: g_y = bias.
//   gemm2: 192 CTAs, REDG-accumulate into bias-preloaded g_y.
//   bcast: 1152 CTAs, TMA bulk stores of g_y over N=576; zeroes g_v at end.

#define B_SZ   64
#define N_SEQ  576
#define C_DIM  768
#define K1     2048
#define LDKV   1536

#define NT1    12              // gemm1: 12 n-tiles of 64
#define KS1    32              // gemm1: 32 k-splits of 64 -> 384 blocks
#define KC1    64
#define NT2    12              // gemm2: 12 n-tiles of 64
#define KS2    16              // gemm2: 16 k-splits of 48 -> 192 blocks
#define KC2    48
#define BC_CH  18              // bcast: 18 chunks of 32 rows -> 1152 blocks

__device__ float g_v[B_SZ * C_DIM];   // zero on entry to every call
__device__ float g_y[B_SZ * C_DIM];   // set to bias by gemm1 every call

// ---- packed f32x2 (FFMA2) ----
__device__ __forceinline__ unsigned long long pack2(float x) {
    unsigned long long r; unsigned xi = __float_as_uint(x);
    asm("mov.b64 %0, {%1, %1};" : "=l"(r) : "r"(xi));
    return r;
}
__device__ __forceinline__ void fma2(unsigned long long& d,
                                     unsigned long long a, unsigned long long b) {
    asm("fma.rn.f32x2 %0, %1, %2, %0;" : "+l"(d) : "l"(a), "l"(b));
}
__device__ __forceinline__ float2 u2f(unsigned long long u) {
    float2 f; asm("mov.b64 {%0, %1}, %2;" : "=f"(f.x), "=f"(f.y) : "l"(u));
    return f;
}
__device__ __forceinline__ void redg_add(float* p, float v) {
    asm volatile("red.global.add.f32 [%0], %1;" :: "l"(p), "f"(v) : "memory");
}
__device__ __forceinline__ uint32_t smem_u32(const void* p) {
    uint32_t a;
    asm("{ .reg .u64 t; cvta.to.shared.u64 t, %1; cvt.u32.u64 %0, t; }" : "=r"(a) : "l"(p));
    return a;
}

// 64-wide tile GEMM body: acc += A[64 x KCHUNK] * B[KCHUNK x 64]
template<int KCHUNK>
__device__ __forceinline__ void gemm_body(
    const float* __restrict__ A, int lda,
    const float* __restrict__ Bm, int ldb,
    float (*As)[68], float (*Bs)[64],
    unsigned long long acc[4][2])
{
    const int tid = threadIdx.x;
    const int tx = tid & 15, ty = tid >> 4;

    for (int kt = 0; kt < KCHUNK; kt += 16) {
        {
            int m = tid >> 2, kq = (tid & 3) * 4;
            float4 a = *(const float4*)&A[m * lda + kt + kq];
            As[kq+0][m] = a.x; As[kq+1][m] = a.y;
            As[kq+2][m] = a.z; As[kq+3][m] = a.w;
        }
        {
            int k = tid >> 4, n4 = (tid & 15) * 4;
            *(float4*)&Bs[k][n4] = *(const float4*)&Bm[(kt + k) * ldb + n4];
        }
        __syncthreads();
        #pragma unroll
        for (int k = 0; k < 16; ++k) {
            float4 a = *(const float4*)&As[k][ty * 4];
            ulonglong2 b = *(const ulonglong2*)&Bs[k][tx * 4];
            unsigned long long a0 = pack2(a.x), a1 = pack2(a.y);
            unsigned long long a2 = pack2(a.z), a3 = pack2(a.w);
            fma2(acc[0][0],a0,b.x); fma2(acc[0][1],a0,b.y);
            fma2(acc[1][0],a1,b.x); fma2(acc[1][1],a1,b.y);
            fma2(acc[2][0],a2,b.x); fma2(acc[2][1],a2,b.y);
            fma2(acc[3][0],a3,b.x); fma2(acc[3][1],a3,b.y);
        }
        __syncthreads();
    }
}

// GEMM1: cnn[64,2048] @ Wkv[:,768:1536], 384 blocks, REDG epilogue -> g_v.
// Prologue (first 192 blocks): g_y = bias.
__global__ void __launch_bounds__(256, 4)
gemm1_kernel(const float* __restrict__ cnn, const float* __restrict__ Wkv,
             const float* __restrict__ bp)
{
    __shared__ float As[16][68];
    __shared__ float Bs[16][64];

    const int tid = threadIdx.x;
    if (blockIdx.x < 192 && tid < 64) {
        int idx = blockIdx.x * 64 + tid;                  // 12288 float4 of g_y
        ((float4*)g_y)[idx] = ((const float4*)bp)[idx % (C_DIM / 4)];
    }

    int ntile = blockIdx.x % NT1;
    int split = blockIdx.x / NT1;
    int n0 = ntile * 64;

    unsigned long long acc[4][2];
    #pragma unroll
    for (int i = 0; i < 4; ++i) { acc[i][0] = 0ull; acc[i][1] = 0ull; }

    gemm_body<KC1>(cnn + split * KC1, K1,
                   Wkv + (size_t)(split * KC1) * LDKV + C_DIM + n0, LDKV,
                   As, Bs, acc);

    const int tx = tid & 15, ty = tid >> 4;
    #pragma unroll
    for (int i = 0; i < 4; ++i) {
        float2 f0 = u2f(acc[i][0]);
        float2 f1 = u2f(acc[i][1]);
        float* p = g_v + (ty * 4 + i) * C_DIM + n0 + tx * 4;
        redg_add(p+0, f0.x); redg_add(p+1, f0.y);
        redg_add(p+2, f1.x); redg_add(p+3, f1.y);
    }
}

// GEMM2: v[64,768] @ Wp, 192 blocks, REDG epilogue into g_y (bias preloaded).
__global__ void __launch_bounds__(256, 4)
gemm2_kernel(const float* __restrict__ Wp)
{
    __shared__ float As[16][68];
    __shared__ float Bs[16][64];

    const int tid = threadIdx.x;
    int ntile = blockIdx.x % NT2;
    int split = blockIdx.x / NT2;
    int n0 = ntile * 64;

    unsigned long long acc[4][2];
    #pragma unroll
    for (int i = 0; i < 4; ++i) { acc[i][0] = 0ull; acc[i][1] = 0ull; }

    gemm_body<KC2>(g_v + split * KC2, C_DIM,
                   Wp + (size_t)(split * KC2) * C_DIM + n0, C_DIM,
                   As, Bs, acc);

    const int tx = tid & 15, ty = tid >> 4;
    #pragma unroll
    for (int i = 0; i < 4; ++i) {
        float2 f0 = u2f(acc[i][0]);
        float2 f1 = u2f(acc[i][1]);
        float* p = g_y + (ty * 4 + i) * C_DIM + n0 + tx * 4;
        redg_add(p+0, f0.x); redg_add(p+1, f0.y);
        redg_add(p+2, f1.x); redg_add(p+3, f1.y);
    }
}

// Broadcast g_y over N=576 via TMA bulk stores; zero g_v for the next call.
// 1152 blocks: b = bx/18, 32 rows per block; stage 8 replicated rows (24 KB),
// 4 bulk stores of 24 KB.
__global__ void __launch_bounds__(256)
bcast_kernel(float* __restrict__ out)
{
    __shared__ __align__(16) float ys[8 * C_DIM];   // 24 KB

    int b     = blockIdx.x / BC_CH;
    int chunk = blockIdx.x % BC_CH;
    const int tid = threadIdx.x;

    const float4* ysrc = (const float4*)(g_y + b * C_DIM);
    #pragma unroll
    for (int i = tid; i < 8 * (C_DIM / 4); i += 256)
        ((float4*)ys)[i] = ysrc[i % (C_DIM / 4)];
    __syncthreads();
    asm volatile("fence.proxy.async.shared::cta;" ::: "memory");

    if (tid < 4) {
        uint32_t s = smem_u32(ys);
        float* g = out + ((size_t)b * N_SEQ + chunk * 32 + tid * 8) * C_DIM;
        asm volatile("cp.async.bulk.global.shared::cta.bulk_group [%0], [%1], %2;"
                     :: "l"(g), "r"(s), "n"(8 * C_DIM * 4) : "memory");
        asm volatile("cp.async.bulk.commit_group;" ::: "memory");
        asm volatile("cp.async.bulk.wait_group 0;" ::: "memory");
    }

    // zero g_v for the next call (first 192 blocks cover 12288 float4)
    if (blockIdx.x < 192 && tid < 64) {
        ((float4*)g_v)[blockIdx.x * 64 + tid] = make_float4(0.f, 0.f, 0.f, 0.f);
    }
}

extern "C" void kernel_launch(void* const* d_in, const int* in_sizes, int n_in,
                              void* d_out, int out_size)
{
    (void)in_sizes; (void)n_in; (void)out_size;
    // Inputs: image_patches, cnn_feature_vector, Wq, Wkv, Wp, bp
    const float* cnn = (const float*)d_in[1];
    const float* Wkv = (const float*)d_in[3];
    const float* Wp  = (const float*)d_in[4];
    const float* bp  = (const float*)d_in[5];
    float* out = (float*)d_out;

    gemm1_kernel<<<NT1 * KS1, 256>>>(cnn, Wkv, bp);   // 384 blocks
    gemm2_kernel<<<NT2 * KS2, 256>>>(Wp);             // 192 blocks
    bcast_kernel<<<B_SZ * BC_CH, 256>>>(out);         // 1152 blocks
}

// round 9
// speedup vs baseline: 1.2252x; 1.1515x over previous
#include <cuda_runtime.h>
#include <cstdint>

// out[b, n, :] = (cnn[b] @ Wkv[:, 768:1536]) @ Wp + bp   (independent of n)
// image_patches and Wq are dead: softmax over kv_len=1 -> attn == 1.
//
// 3 launches:
//   gemm1: 384 CTAs, double-buffered, red.v4 accumulate v into g_v
//          (g_v == 0 on entry: static init call 1, re-zeroed by bcast each
//          call). Prologue: g_y = bias.
//   gemm2: 192 CTAs, double-buffered, red.v4 accumulate into bias-loaded g_y.
//   bcast: 576 CTAs x 8 TMA bulk stores; zeroes g_v at end.

#define B_SZ   64
#define N_SEQ  576
#define C_DIM  768
#define K1     2048
#define LDKV   1536

#define NT1    12              // gemm1: 12 n-tiles of 64
#define KS1    32              // gemm1: 32 k-splits of 64 -> 384 blocks
#define KC1    64
#define NT2    12              // gemm2: 12 n-tiles of 64
#define KS2    16              // gemm2: 16 k-splits of 48 -> 192 blocks
#define KC2    48

__device__ float g_v[B_SZ * C_DIM];   // zero on entry to every call
__device__ float g_y[B_SZ * C_DIM];   // set to bias by gemm1 every call

// ---- packed f32x2 (FFMA2) ----
__device__ __forceinline__ unsigned long long pack2(float x) {
    unsigned long long r; unsigned xi = __float_as_uint(x);
    asm("mov.b64 %0, {%1, %1};" : "=l"(r) : "r"(xi));
    return r;
}
__device__ __forceinline__ void fma2(unsigned long long& d,
                                     unsigned long long a, unsigned long long b) {
    asm("fma.rn.f32x2 %0, %1, %2, %0;" : "+l"(d) : "l"(a), "l"(b));
}
__device__ __forceinline__ float2 u2f(unsigned long long u) {
    float2 f; asm("mov.b64 {%0, %1}, %2;" : "=f"(f.x), "=f"(f.y) : "l"(u));
    return f;
}
// Vector reduction: 1 LTS atomic op for 4 floats (sm_90+).
__device__ __forceinline__ void redg_add4(float* p, float a, float b, float c, float d) {
    asm volatile("red.global.add.v4.f32 [%0], {%1, %2, %3, %4};"
                 :: "l"(p), "f"(a), "f"(b), "f"(c), "f"(d) : "memory");
}
__device__ __forceinline__ uint32_t smem_u32(const void* p) {
    uint32_t a;
    asm("{ .reg .u64 t; cvta.to.shared.u64 t, %1; cvt.u32.u64 %0, t; }" : "=r"(a) : "l"(p));
    return a;
}

// ---------------------------------------------------------------------------
// Double-buffered 64-wide tile GEMM body:
//   acc += A[64 x KCHUNK] * B[KCHUNK x 64]
// Register-prefetch tile t+1 while computing tile t from smem.
// ---------------------------------------------------------------------------
template<int KCHUNK>
__device__ __forceinline__ void gemm_body_db(
    const float* __restrict__ A, int lda,
    const float* __restrict__ Bm, int ldb,
    float (*As)[68], float (*Bs)[64],
    unsigned long long acc[4][2])
{
    const int tid = threadIdx.x;
    const int tx = tid & 15, ty = tid >> 4;
    const int m  = tid >> 2, kq = (tid & 3) * 4;   // A-load coords
    const int kb = tid >> 4, n4 = (tid & 15) * 4;  // B-load coords

    float4 aReg = *(const float4*)&A[m * lda + kq];
    float4 bReg = *(const float4*)&Bm[kb * ldb + n4];

    #pragma unroll
    for (int kt = 0; kt < KCHUNK; kt += 16) {
        // commit prefetched tile to smem
        As[kq + 0][m] = aReg.x; As[kq + 1][m] = aReg.y;
        As[kq + 2][m] = aReg.z; As[kq + 3][m] = aReg.w;
        *(float4*)&Bs[kb][n4] = bReg;
        __syncthreads();

        // prefetch next tile (overlaps with compute below)
        if (kt + 16 < KCHUNK) {
            aReg = *(const float4*)&A[m * lda + kt + 16 + kq];
            bReg = *(const float4*)&Bm[(kt + 16 + kb) * ldb + n4];
        }

        #pragma unroll
        for (int k = 0; k < 16; ++k) {
            float4 a = *(const float4*)&As[k][ty * 4];
            ulonglong2 b = *(const ulonglong2*)&Bs[k][tx * 4];
            unsigned long long a0 = pack2(a.x), a1 = pack2(a.y);
            unsigned long long a2 = pack2(a.z), a3 = pack2(a.w);
            fma2(acc[0][0],a0,b.x); fma2(acc[0][1],a0,b.y);
            fma2(acc[1][0],a1,b.x); fma2(acc[1][1],a1,b.y);
            fma2(acc[2][0],a2,b.x); fma2(acc[2][1],a2,b.y);
            fma2(acc[3][0],a3,b.x); fma2(acc[3][1],a3,b.y);
        }
        __syncthreads();
    }
}

// GEMM1: cnn[64,2048] @ Wkv[:,768:1536], 384 blocks, red.v4 epilogue -> g_v.
// Prologue (first 192 blocks): g_y = bias.
__global__ void __launch_bounds__(256, 3)
gemm1_kernel(const float* __restrict__ cnn, const float* __restrict__ Wkv,
             const float* __restrict__ bp)
{
    __shared__ float As[16][68];
    __shared__ float Bs[16][64];

    const int tid = threadIdx.x;
    if (blockIdx.x < 192 && tid < 64) {
        int idx = blockIdx.x * 64 + tid;                  // 12288 float4 of g_y
        ((float4*)g_y)[idx] = ((const float4*)bp)[idx % (C_DIM / 4)];
    }

    int ntile = blockIdx.x % NT1;
    int split = blockIdx.x / NT1;
    int n0 = ntile * 64;

    unsigned long long acc[4][2];
    #pragma unroll
    for (int i = 0; i < 4; ++i) { acc[i][0] = 0ull; acc[i][1] = 0ull; }

    gemm_body_db<KC1>(cnn + split * KC1, K1,
                      Wkv + (size_t)(split * KC1) * LDKV + C_DIM + n0, LDKV,
                      As, Bs, acc);

    const int tx = tid & 15, ty = tid >> 4;
    #pragma unroll
    for (int i = 0; i < 4; ++i) {
        float2 f0 = u2f(acc[i][0]);
        float2 f1 = u2f(acc[i][1]);
        redg_add4(g_v + (ty * 4 + i) * C_DIM + n0 + tx * 4,
                  f0.x, f0.y, f1.x, f1.y);
    }
}

// GEMM2: v[64,768] @ Wp, 192 blocks, red.v4 epilogue into g_y (bias preloaded).
__global__ void __launch_bounds__(256, 3)
gemm2_kernel(const float* __restrict__ Wp)
{
    __shared__ float As[16][68];
    __shared__ float Bs[16][64];

    const int tid = threadIdx.x;
    int ntile = blockIdx.x % NT2;
    int split = blockIdx.x / NT2;
    int n0 = ntile * 64;

    unsigned long long acc[4][2];
    #pragma unroll
    for (int i = 0; i < 4; ++i) { acc[i][0] = 0ull; acc[i][1] = 0ull; }

    gemm_body_db<KC2>(g_v + split * KC2, C_DIM,
                      Wp + (size_t)(split * KC2) * C_DIM + n0, C_DIM,
                      As, Bs, acc);

    const int tx = tid & 15, ty = tid >> 4;
    #pragma unroll
    for (int i = 0; i < 4; ++i) {
        float2 f0 = u2f(acc[i][0]);
        float2 f1 = u2f(acc[i][1]);
        redg_add4(g_y + (ty * 4 + i) * C_DIM + n0 + tx * 4,
                  f0.x, f0.y, f1.x, f1.y);
    }
}

// Broadcast g_y over N=576 via TMA bulk stores; zero g_v for the next call.
// 576 blocks x 512 threads: b = bx/9, 64 rows per block; stage 8 replicated
// rows (24 KB) once, then 8 bulk stores of 24 KB (8 rows each).
__global__ void __launch_bounds__(512)
bcast_kernel(float* __restrict__ out)
{
    __shared__ __align__(16) float ys[8 * C_DIM];   // 24 KB

    int b     = blockIdx.x / 9;
    int chunk = blockIdx.x % 9;
    const int tid = threadIdx.x;

    const float4* ysrc = (const float4*)(g_y + b * C_DIM);
    #pragma unroll
    for (int i = tid; i < 8 * (C_DIM / 4); i += 512)
        ((float4*)ys)[i] = ysrc[i % (C_DIM / 4)];
    __syncthreads();
    asm volatile("fence.proxy.async.shared::cta;" ::: "memory");

    if (tid < 8) {
        uint32_t s = smem_u32(ys);
        float* g = out + ((size_t)b * N_SEQ + chunk * 64 + tid * 8) * C_DIM;
        asm volatile("cp.async.bulk.global.shared::cta.bulk_group [%0], [%1], %2;"
                     :: "l"(g), "r"(s), "n"(8 * C_DIM * 4) : "memory");
        asm volatile("cp.async.bulk.commit_group;" ::: "memory");
        asm volatile("cp.async.bulk.wait_group 0;" ::: "memory");
    }

    // zero g_v for the next call (first 192 blocks cover 12288 float4)
    if (blockIdx.x < 192 && tid < 64) {
        ((float4*)g_v)[blockIdx.x * 64 + tid] = make_float4(0.f, 0.f, 0.f, 0.f);
    }
}

extern "C" void kernel_launch(void* const* d_in, const int* in_sizes, int n_in,
                              void* d_out, int out_size)
{
    (void)in_sizes; (void)n_in; (void)out_size;
    // Inputs: image_patches, cnn_feature_vector, Wq, Wkv, Wp, bp
    const float* cnn = (const float*)d_in[1];
    const float* Wkv = (const float*)d_in[3];
    const float* Wp  = (const float*)d_in[4];
    const float* bp  = (const float*)d_in[5];
    float* out = (float*)d_out;

    gemm1_kernel<<<NT1 * KS1, 256>>>(cnn, Wkv, bp);   // 384 blocks
    gemm2_kernel<<<NT2 * KS2, 256>>>(Wp);             // 192 blocks
    bcast_kernel<<<B_SZ * 9, 512>>>(out);             // 576 blocks
}